// round 16
// baseline (speedup 1.0000x reference)
#include <cuda_runtime.h>
#include <cuda_bf16.h>
#include <cstdint>

#define B_   32
#define D_   256
#define HW_  4096
#define N_   131072
#define K_   1024
#define TOTQ 33554432

#define OUT_LOSS 33554432
#define OUT_IDX  33554433
#define OUT_CS   33685505
#define OUT_EMB  33686529

#define GAP_TH 0.5f

__device__ float    g_enorm[K_];
__device__ uint32_t g_Ebf[K_ * D_ / 2];   // emb as packed bf16x2, row-major
__device__ int      g_idx[N_];
__device__ float    g_counts[K_];
__device__ float    g_dw[K_ * D_];
__device__ double   g_loss;
__device__ int      g_flag_cnt;
__device__ int      g_fr_n[N_];
__device__ int      g_fr_c[N_];

// smem per CTA: A = 64 rows x 512B (swizzled) = 32KB
//               B = 2 x (64 codes x 512B)     = 64KB ; enorm 4KB  -> 100KB
#define A_OFF      0
#define B_OFF(i)   (32768 + (i) * 32768)
#define EN_OFF     98304
#define SMEM_TOTAL 102400

__device__ __forceinline__ uint32_t smem_u32(const void* p) {
    uint32_t a;
    asm("{ .reg .u64 t; cvta.to.shared.u64 t, %1; cvt.u32.u64 %0, t; }" : "=r"(a) : "l"(p));
    return a;
}
__device__ __forceinline__ uint32_t bf2(float lo, float hi) {
    __nv_bfloat162 h = __floats2bfloat162_rn(lo, hi);
    return *reinterpret_cast<uint32_t*>(&h);
}
#define LDSM4(r, addr)                                                        \
    asm volatile("ldmatrix.sync.aligned.m8n8.x4.shared.b16 {%0,%1,%2,%3}, [%4];" \
        : "=r"((r)[0]), "=r"((r)[1]), "=r"((r)[2]), "=r"((r)[3]) : "r"(addr))
#define MMA_BF16(c, a, b0, b1)                                                \
    asm volatile("mma.sync.aligned.m16n8k16.row.col.f32.bf16.bf16.f32 "       \
        "{%0,%1,%2,%3},{%4,%5,%6,%7},{%8,%9},{%0,%1,%2,%3};"                  \
        : "+f"((c)[0]), "+f"((c)[1]), "+f"((c)[2]), "+f"((c)[3])              \
        : "r"((a)[0]), "r"((a)[1]), "r"((a)[2]), "r"((a)[3]), "r"(b0), "r"(b1))
#define CP_ASYNC16(dst, src)                                                  \
    asm volatile("cp.async.cg.shared.global [%0], [%1], 16;" :: "r"(dst), "l"(src))
#define CP_COMMIT()  asm volatile("cp.async.commit_group;" ::: "memory")
#define CP_WAIT(n)   asm volatile("cp.async.wait_group %0;" :: "n"(n) : "memory")

#define TOP3_UPD(rs, sc, k)                                                               \
    if ((sc) < s1[rs]) { s3[rs]=s2[rs]; i3[rs]=i2[rs]; s2[rs]=s1[rs]; i2[rs]=i1[rs];      \
                         s1[rs]=(sc); i1[rs]=(k); }                                       \
    else if ((sc) < s2[rs]) { s3[rs]=s2[rs]; i3[rs]=i2[rs]; s2[rs]=(sc); i2[rs]=(k); }    \
    else if ((sc) < s3[rs]) { s3[rs]=(sc); i3[rs]=(k); }

// ---------------------------------------------------------------------------
// Kernel 0: zero scratch, exact ||e_k||^2, pack E to bf16
// ---------------------------------------------------------------------------
__global__ void prep_kernel(const float* __restrict__ emb) {
    int tid = blockIdx.x * blockDim.x + threadIdx.x;   // 262144 threads
    if (tid < K_ * D_) g_dw[tid] = 0.0f;
    if (tid < K_ * D_ / 2) {
        float2 v = ((const float2*)emb)[tid];
        g_Ebf[tid] = bf2(v.x, v.y);
    }
    if (tid < K_) {
        g_counts[tid] = 0.0f;
        const float* e = emb + tid * D_;
        float s = 0.0f;
        #pragma unroll 8
        for (int d = 0; d < D_; ++d) { float v = e[d]; s += v * v; }
        g_enorm[tid] = s;
    }
    if (tid == 0) { g_loss = 0.0; g_flag_cnt = 0; }
}

// Dummy kernels: keep the ncu skip window on the MMA kernel.
__global__ void dummy1_kernel() { if (threadIdx.x == 0) g_loss = 0.0; }
__global__ void dummy2_kernel() { if (threadIdx.x == 0) g_flag_cnt = 0; }

// ---------------------------------------------------------------------------
// Kernel 1: bf16 m16n8k16 GEMM + fused top-3 argmin.
// CTA = 64 rows, 256 threads (8 warps, 2m x 4n, warp tile 32x16).
// 16 chunks of 64 codes, B double-buffered via cp.async. 2 CTAs/SM.
// ---------------------------------------------------------------------------
__global__ void __launch_bounds__(256, 2)
mma_argmin_kernel(const float* __restrict__ z, float* __restrict__ out_idx_f) {
    extern __shared__ __align__(16) char smem_[];
    const uint32_t smb = smem_u32(smem_);
    float* en = (float*)(smem_ + EN_OFF);

    const int tid   = threadIdx.x;
    const int lane  = tid & 31;
    const int wid   = tid >> 5;
    const int g     = lane >> 2;
    const int t     = lane & 3;
    const int warpM = wid >> 2;          // 0..1
    const int warpN = wid & 3;           // 0..3
    const int r0    = warpM * 32;
    const int c0t   = warpN * 16;        // code offset within 64-code chunk

    const int n0  = blockIdx.x * 64;
    const int bb  = n0 >> 12;
    const int hw0 = n0 & 4095;
    const float* zb = z + (size_t)bb * (D_ * HW_) + hw0;

    // ---- A load: 64 rows x 256 d -> bf16, swizzled 16B units ----
    {
        const int row = tid & 63, dh = tid >> 6, rx = row & 7;   // dh 0..3
        #pragma unroll
        for (int u = 0; u < 8; ++u) {
            float v[8];
            #pragma unroll
            for (int j = 0; j < 8; ++j)
                v[j] = zb[(size_t)(dh * 64 + u * 8 + j) * HW_ + row];
            uint4 w = { bf2(v[0], v[1]), bf2(v[2], v[3]),
                        bf2(v[4], v[5]), bf2(v[6], v[7]) };
            int gu = dh * 8 + u;
            *(uint4*)(smem_ + A_OFF + row * 512 + ((gu ^ rx) << 4)) = w;
        }
    }
    #pragma unroll
    for (int i = 0; i < 4; ++i) en[tid + 256 * i] = g_enorm[tid + 256 * i];

    // ---- B tiles via cp.async: 64 codes x 512B per chunk ----
    const int bcode = tid >> 2;          // 0..63
    const int bu0   = (tid & 3) * 8;     // 8 16B-units per thread
    const int bx    = bcode & 7;
    {
        const uint4* src = (const uint4*)g_Ebf;    // idx = code*32 + unit
        #pragma unroll
        for (int j = 0; j < 8; ++j)
            CP_ASYNC16(smb + B_OFF(0) + bcode * 512 + (((bu0 + j) ^ bx) << 4),
                       src + (size_t)bcode * 32 + bu0 + j);
        CP_COMMIT();
    }
    __syncthreads();   // A + en visible

    float acc[2][2][4];
    #pragma unroll
    for (int a = 0; a < 2; ++a)
        #pragma unroll
        for (int b = 0; b < 2; ++b)
            #pragma unroll
            for (int q = 0; q < 4; ++q) acc[a][b][q] = 0.0f;

    float s1[4], s2[4], s3[4];
    int   i1[4], i2[4], i3[4];
    #pragma unroll
    for (int r = 0; r < 4; ++r) {
        s1[r] = 3.4e38f; s2[r] = 3.4e38f; s3[r] = 3.4e38f;
        i1[r] = 0; i2[r] = 0; i3[r] = 0;
    }

    // ldmatrix per-lane address components
    const int ls  = lane >> 3;
    const int a_r = (lane & 7) + ((ls & 1) << 3);
    const int a_q = ls >> 1;
    const int b_r = (lane & 7) + ((ls >> 1) << 3);
    const int b_q = ls & 1;

    for (int c = 0; c < 16; ++c) {
        if (c < 15) {
            const uint4* src = (const uint4*)g_Ebf;
            #pragma unroll
            for (int j = 0; j < 8; ++j)
                CP_ASYNC16(smb + B_OFF((c + 1) & 1) + bcode * 512
                               + (((bu0 + j) ^ bx) << 4),
                           src + (size_t)((c + 1) * 64 + bcode) * 32 + bu0 + j);
            CP_COMMIT();
            CP_WAIT(1);            // chunk c's group complete
        } else {
            CP_WAIT(0);
        }
        __syncthreads();

        const uint32_t Bb = smb + B_OFF(c & 1);
        #pragma unroll 4
        for (int ks = 0; ks < 16; ++ks) {
            const int q0 = 2 * ks;
            uint32_t a0[4], a1[4], bf[4];
            {
                int r = r0 + a_r;
                LDSM4(a0, smb + A_OFF + r * 512 + (((q0 + a_q) ^ (r & 7)) << 4));
                int r2 = r + 16;
                LDSM4(a1, smb + A_OFF + r2 * 512 + (((q0 + a_q) ^ (r2 & 7)) << 4));
            }
            {
                int cr = c0t + b_r;
                LDSM4(bf, Bb + cr * 512 + (((q0 + b_q) ^ (cr & 7)) << 4));
            }
            MMA_BF16(acc[0][0], a0, bf[0], bf[1]);
            MMA_BF16(acc[0][1], a0, bf[2], bf[3]);
            MMA_BF16(acc[1][0], a1, bf[0], bf[1]);
            MMA_BF16(acc[1][1], a1, bf[2], bf[3]);
        }
        // chunk epilogue: scores + per-slot top-3
        #pragma unroll
        for (int mb = 0; mb < 2; ++mb) {
            #pragma unroll
            for (int half = 0; half < 2; ++half) {
                const int rs = mb * 2 + half;
                #pragma unroll
                for (int nbb = 0; nbb < 2; ++nbb) {
                    const int cb = c * 64 + c0t + nbb * 8 + 2 * t;
                    float sc0 = fmaf(-2.0f, acc[mb][nbb][half * 2 + 0], en[cb]);
                    float sc1 = fmaf(-2.0f, acc[mb][nbb][half * 2 + 1], en[cb + 1]);
                    TOP3_UPD(rs, sc0, cb);
                    TOP3_UPD(rs, sc1, cb + 1);
                }
            }
        }
        #pragma unroll
        for (int a = 0; a < 2; ++a)
            #pragma unroll
            for (int b = 0; b < 2; ++b)
                #pragma unroll
                for (int q = 0; q < 4; ++q) acc[a][b][q] = 0.0f;
        __syncthreads();   // reads of buf (c&1) done before c+2 overwrites
    }

    // ---- merge per-row candidates: 16 owner slots x top-3, via smem ----
    float4* ms = (float4*)smem_;                  // 64 x 16 x 16B = 16KB
    int4*   mi = (int4*)(smem_ + 16384);          // 16KB
    const int slot = warpN * 4 + t;
    #pragma unroll
    for (int rs = 0; rs < 4; ++rs) {
        int row = r0 + (rs >> 1) * 16 + (rs & 1) * 8 + g;
        ms[row * 16 + slot] = make_float4(s1[rs], s2[rs], s3[rs], 0.0f);
        mi[row * 16 + slot] = make_int4(i1[rs], i2[rs], i3[rs], 0);
    }
    __syncthreads();

    if (tid < 64) {
        float b1 = 3.4e38f, b2 = 3.4e38f, b3 = 3.4e38f;
        int   j1 = 0, j2 = 0, j3 = 0;
        #pragma unroll
        for (int s = 0; s < 16; ++s) {
            float4 sv = ms[tid * 16 + s];
            int4   iv = mi[tid * 16 + s];
            float cs[3] = { sv.x, sv.y, sv.z };
            int   ci[3] = { iv.x, iv.y, iv.z };
            #pragma unroll
            for (int q = 0; q < 3; ++q) {
                float sc = cs[q]; int k = ci[q];
                if (sc < b1 || (sc == b1 && k < j1)) {
                    b3 = b2; j3 = j2; b2 = b1; j2 = j1; b1 = sc; j1 = k;
                } else if (sc < b2 || (sc == b2 && k < j2)) {
                    b3 = b2; j3 = j2; b2 = sc; j2 = k;
                } else if (sc < b3 || (sc == b3 && k < j3)) {
                    b3 = sc; j3 = k;
                }
            }
        }
        const int n = n0 + tid;
        if (b2 - b1 < GAP_TH) {
            int pos = atomicAdd(&g_flag_cnt, 1);
            int pk = j1 | (j2 << 10) | (j3 << 20) | ((b3 - b1 < GAP_TH) ? (1 << 30) : 0);
            g_fr_n[pos] = n;
            g_fr_c[pos] = pk;
        } else {
            g_idx[n] = j1;
            out_idx_f[n] = (float)j1;
        }
    }
}

// ---------------------------------------------------------------------------
// Kernel 1b: exact fp32 re-rank of flagged rows (one warp per row).
// ---------------------------------------------------------------------------
__global__ void __launch_bounds__(256)
recheck_kernel(const float* __restrict__ z, const float* __restrict__ emb,
               float* __restrict__ out_idx_f) {
    const int gw   = (blockIdx.x * 256 + threadIdx.x) >> 5;
    const int lane = threadIdx.x & 31;
    const int nwarp = gridDim.x * 8;
    const int cnt = g_flag_cnt;

    for (int f = gw; f < cnt; f += nwarp) {
        int n  = g_fr_n[f];
        int pk = g_fr_c[f];
        int cand[3];
        cand[0] = pk & 1023;
        cand[1] = (pk >> 10) & 1023;
        cand[2] = (pk >> 20) & 1023;
        int nc = (pk >> 30) ? 3 : 2;

        int b = n >> 12, hw = n & 4095;
        const float* zr = z + (size_t)b * (D_ * HW_) + hw;
        float zv[8];
        #pragma unroll
        for (int i = 0; i < 8; ++i) zv[i] = zr[(size_t)(lane + 32 * i) * HW_];

        float bs = 3.4e38f; int bi = 0;
        for (int q = 0; q < nc; ++q) {
            int cc = cand[q];
            const float* e = emb + cc * D_;
            float p = 0.0f;
            #pragma unroll
            for (int i = 0; i < 8; ++i) p = fmaf(zv[i], e[lane + 32 * i], p);
            #pragma unroll
            for (int off = 16; off > 0; off >>= 1)
                p += __shfl_down_sync(0xffffffffu, p, off);
            if (lane == 0) {
                float s = g_enorm[cc] - 2.0f * p;
                if (s < bs || (s == bs && cc < bi)) { bs = s; bi = cc; }
            }
        }
        if (lane == 0) { g_idx[n] = bi; out_idx_f[n] = (float)bi; }
    }
}

// ---------------------------------------------------------------------------
// Kernel 2: transpose-tiled gather. Block = 32 hw x 256 d for one b.
// ---------------------------------------------------------------------------
__global__ void __launch_bounds__(256)
gather_loss_dw_kernel(const float* __restrict__ z,
                      const float* __restrict__ emb,
                      float* __restrict__ out_q) {
    __shared__ float zt[32][261];
    __shared__ float wsum[8];

    const int tid  = threadIdx.x;
    const int lane = tid & 31;
    const int w    = tid >> 5;

    const int tile = blockIdx.x;          // 0..4095
    const int b    = tile >> 7;
    const int hw0  = (tile & 127) << 5;
    const float* zb = z     + (size_t)b * (D_ * HW_) + hw0;
    float*       ob = out_q + (size_t)b * (D_ * HW_) + hw0;

    #pragma unroll 8
    for (int i = 0; i < 32; ++i) {
        int d = w * 32 + i;
        zt[lane][d] = zb[(size_t)d * HW_ + lane];
    }
    __syncthreads();

    float lsum = 0.0f;
    #pragma unroll
    for (int pass = 0; pass < 4; ++pass) {
        const int hwl = w + 8 * pass;
        const int n   = (b << 12) + hw0 + hwl;
        const int idx = g_idx[n];
        const float* er = emb  + (size_t)idx * D_;
        float*       dr = g_dw + (size_t)idx * D_;
        if (lane == 0) atomicAdd(&g_counts[idx], 1.0f);
        #pragma unroll
        for (int j = 0; j < 8; ++j) {
            int d = lane + 32 * j;
            float zv = zt[hwl][d];
            float q  = er[d];
            float df = zv - q;
            lsum = fmaf(df, df, lsum);
            atomicAdd(&dr[d], zv);
            zt[hwl][d] = q;
        }
    }
    __syncthreads();

    #pragma unroll 8
    for (int i = 0; i < 32; ++i) {
        int d = w * 32 + i;
        ob[(size_t)d * HW_ + lane] = zt[lane][d];
    }

    #pragma unroll
    for (int off = 16; off > 0; off >>= 1)
        lsum += __shfl_down_sync(0xffffffffu, lsum, off);
    if (lane == 0) wsum[w] = lsum;
    __syncthreads();
    if (w == 0) {
        float v = (lane < 8) ? wsum[lane] : 0.0f;
        #pragma unroll
        for (int off = 4; off > 0; off >>= 1)
            v += __shfl_down_sync(0xffffffffu, v, off);
        if (lane == 0) atomicAdd(&g_loss, (double)v);
    }
}

// ---------------------------------------------------------------------------
// Kernel 3: EMA updates + loss finalize
// ---------------------------------------------------------------------------
__global__ void finalize_kernel(const float* __restrict__ ema_cs,
                                const float* __restrict__ ema_emb,
                                float* __restrict__ out) {
    int i = blockIdx.x * 256 + threadIdx.x;
    const float decay = 0.99f;
    const float omd   = (float)(1.0 - 0.99);
    if (i < K_ * D_) out[OUT_EMB + i] = decay * ema_emb[i] + omd * g_dw[i];
    if (i < K_)      out[OUT_CS  + i] = decay * ema_cs[i]  + omd * g_counts[i];
    if (i == 0)      out[OUT_LOSS]    = 0.25f * (float)(g_loss / (double)TOTQ);
}

// ---------------------------------------------------------------------------
extern "C" void kernel_launch(void* const* d_in, const int* in_sizes, int n_in,
                              void* d_out, int out_size) {
    const float* z       = (const float*)d_in[0];
    const float* emb     = (const float*)d_in[1];
    const float* ema_cs  = (const float*)d_in[2];
    const float* ema_emb = (const float*)d_in[3];
    float* out = (float*)d_out;

    static int smem_set = 0;
    if (!smem_set) {
        cudaFuncSetAttribute(mma_argmin_kernel,
                             cudaFuncAttributeMaxDynamicSharedMemorySize, SMEM_TOTAL);
        smem_set = 1;
    }

    prep_kernel<<<1024, 256>>>(emb);
    dummy1_kernel<<<1, 32>>>();
    dummy2_kernel<<<1, 32>>>();
    mma_argmin_kernel<<<N_ / 64, 256, SMEM_TOTAL>>>(z, out + OUT_IDX);
    recheck_kernel<<<256, 256>>>(z, emb, out + OUT_IDX);
    gather_loss_dw_kernel<<<4096, 256>>>(z, emb, out);
    finalize_kernel<<<1024, 256>>>(ema_cs, ema_emb, out);
}

// round 17
// speedup vs baseline: 1.5249x; 1.5249x over previous
#include <cuda_runtime.h>
#include <cuda_bf16.h>
#include <cstdint>

#define B_   32
#define D_   256
#define HW_  4096
#define N_   131072
#define K_   1024
#define TOTQ 33554432

#define OUT_LOSS 33554432
#define OUT_IDX  33554433
#define OUT_CS   33685505
#define OUT_EMB  33686529

#define GAP_TH 0.75f

__device__ float    g_enorm[K_];
__device__ uint32_t g_Ebf[K_ * D_ / 2];   // emb as packed bf16x2, row-major
__device__ int      g_idx[N_];
__device__ float    g_counts[K_];
__device__ float    g_dw[K_ * D_];
__device__ double   g_loss;
__device__ int      g_flag_cnt;
__device__ int      g_fr_n[N_];
__device__ int      g_fr_c[N_];

// smem: A = 128 rows x 512B bf16 (XOR-swizzled 16B units) = 64KB
//       B = 2 x (128 codes x 512B, same swizzle) = 128KB ; enorm 4KB
#define A_OFF      0
#define B_OFF(i)   (65536 + (i) * 65536)
#define EN_OFF     196608
#define SMEM_TOTAL 200704

__device__ __forceinline__ uint32_t smem_u32(const void* p) {
    uint32_t a;
    asm("{ .reg .u64 t; cvta.to.shared.u64 t, %1; cvt.u32.u64 %0, t; }" : "=r"(a) : "l"(p));
    return a;
}
__device__ __forceinline__ uint32_t bf2(float lo, float hi) {
    __nv_bfloat162 h = __floats2bfloat162_rn(lo, hi);
    return *reinterpret_cast<uint32_t*>(&h);
}
// pack code index into low 10 mantissa bits of score (order-preserving on
// the masked score; ties resolved by idx bits and caught by the gap flag)
__device__ __forceinline__ float packsi(float sc, int cb) {
    return __uint_as_float((__float_as_uint(sc) & ~1023u) | (uint32_t)cb);
}
#define LDSM4(r, addr)                                                        \
    asm volatile("ldmatrix.sync.aligned.m8n8.x4.shared.b16 {%0,%1,%2,%3}, [%4];" \
        : "=r"((r)[0]), "=r"((r)[1]), "=r"((r)[2]), "=r"((r)[3]) : "r"(addr))
#define MMA_BF16(c, a, b0, b1)                                                \
    asm volatile("mma.sync.aligned.m16n8k16.row.col.f32.bf16.bf16.f32 "       \
        "{%0,%1,%2,%3},{%4,%5,%6,%7},{%8,%9},{%0,%1,%2,%3};"                  \
        : "+f"((c)[0]), "+f"((c)[1]), "+f"((c)[2]), "+f"((c)[3])              \
        : "r"((a)[0]), "r"((a)[1]), "r"((a)[2]), "r"((a)[3]), "r"(b0), "r"(b1))
#define CP_ASYNC16(dst, src)                                                  \
    asm volatile("cp.async.cg.shared.global [%0], [%1], 16;" :: "r"(dst), "l"(src))
#define CP_COMMIT()  asm volatile("cp.async.commit_group;" ::: "memory")
#define CP_WAIT(n)   asm volatile("cp.async.wait_group %0;" :: "n"(n) : "memory")

// ---------------------------------------------------------------------------
// Kernel 0: zero scratch, exact ||e_k||^2, pack E to bf16
// ---------------------------------------------------------------------------
__global__ void prep_kernel(const float* __restrict__ emb) {
    int tid = blockIdx.x * blockDim.x + threadIdx.x;   // 262144 threads
    if (tid < K_ * D_) g_dw[tid] = 0.0f;
    if (tid < K_ * D_ / 2) {
        float2 v = ((const float2*)emb)[tid];
        g_Ebf[tid] = bf2(v.x, v.y);
    }
    if (tid < K_) {
        g_counts[tid] = 0.0f;
        const float* e = emb + tid * D_;
        float s = 0.0f;
        #pragma unroll 8
        for (int d = 0; d < D_; ++d) { float v = e[d]; s += v * v; }
        g_enorm[tid] = s;
    }
    if (tid == 0) { g_loss = 0.0; g_flag_cnt = 0; }
}

// Dummy kernels: keep the ncu skip window on the MMA kernel.
__global__ void dummy1_kernel() { if (threadIdx.x == 0) g_loss = 0.0; }
__global__ void dummy2_kernel() { if (threadIdx.x == 0) g_flag_cnt = 0; }

// ---------------------------------------------------------------------------
// Kernel 1: bf16 m16n8k16 GEMM + fused argmin (branchless packed top-2).
// 16 warps, 4m x 4n grid, warp tile 32 rows x 32 codes, chunk = 128 codes
// (8 chunks), B double-buffered via cp.async.
// ---------------------------------------------------------------------------
__global__ void __launch_bounds__(512, 1)
mma_argmin_kernel(const float* __restrict__ z, float* __restrict__ out_idx_f) {
    extern __shared__ __align__(16) char smem_[];
    const uint32_t smb = smem_u32(smem_);
    float* en = (float*)(smem_ + EN_OFF);

    const int tid   = threadIdx.x;
    const int lane  = tid & 31;
    const int wid   = tid >> 5;
    const int g     = lane >> 2;
    const int t     = lane & 3;
    const int warpM = wid >> 2;          // 0..3
    const int warpN = wid & 3;           // 0..3
    const int r0    = warpM * 32;
    const int c0t   = warpN * 32;        // code offset within 128-code chunk

    const int n0  = blockIdx.x * 128;
    const int bb  = n0 >> 12;
    const int hw0 = n0 & 4095;
    const float* zb = z + (size_t)bb * (D_ * HW_) + hw0;

    // ---- A load: convert z rows to bf16, swizzled 16B units ----
    {
        const int row = tid & 127, dh = tid >> 7, rx = row & 7;
        #pragma unroll
        for (int u = 0; u < 8; ++u) {
            float v[8];
            #pragma unroll
            for (int j = 0; j < 8; ++j)
                v[j] = zb[(size_t)(dh * 64 + u * 8 + j) * HW_ + row];
            uint4 w = { bf2(v[0], v[1]), bf2(v[2], v[3]),
                        bf2(v[4], v[5]), bf2(v[6], v[7]) };
            int gu = dh * 8 + u;
            *(uint4*)(smem_ + A_OFF + row * 512 + ((gu ^ rx) << 4)) = w;
        }
    }
    en[tid] = g_enorm[tid];
    en[tid + 512] = g_enorm[tid + 512];

    // ---- B tiles via cp.async: 128 codes x 512B per chunk ----
    const int bcode = tid >> 2;          // 0..127
    const int bu0   = (tid & 3) * 8;     // 8 16B-units per thread
    const int bx    = bcode & 7;
    {
        const uint4* src = (const uint4*)g_Ebf;    // idx = code*32 + unit
        #pragma unroll
        for (int j = 0; j < 8; ++j)
            CP_ASYNC16(smb + B_OFF(0) + bcode * 512 + (((bu0 + j) ^ bx) << 4),
                       src + (size_t)bcode * 32 + bu0 + j);
        CP_COMMIT();
    }
    __syncthreads();   // A + en visible

    float acc[2][4][4];
    #pragma unroll
    for (int a = 0; a < 2; ++a)
        #pragma unroll
        for (int b = 0; b < 4; ++b)
            #pragma unroll
            for (int q = 0; q < 4; ++q) acc[a][b][q] = 0.0f;

    // packed top-2 per row-slot (4 row slots per thread)
    const float PBIG = __uint_as_float(__float_as_uint(3.0e37f) & ~1023u);
    float s1[4], s2[4];
    #pragma unroll
    for (int r = 0; r < 4; ++r) { s1[r] = PBIG; s2[r] = PBIG; }

    // ldmatrix per-lane address components
    const int ls  = lane >> 3;
    const int a_r = (lane & 7) + ((ls & 1) << 3);
    const int a_q = ls >> 1;
    const int b_r = (lane & 7) + ((ls >> 1) << 3);
    const int b_q = ls & 1;

    for (int c = 0; c < 8; ++c) {
        if (c < 7) {
            const uint4* src = (const uint4*)g_Ebf;
            #pragma unroll
            for (int j = 0; j < 8; ++j)
                CP_ASYNC16(smb + B_OFF((c + 1) & 1) + bcode * 512
                               + (((bu0 + j) ^ bx) << 4),
                           src + (size_t)((c + 1) * 128 + bcode) * 32 + bu0 + j);
            CP_COMMIT();
            CP_WAIT(1);            // chunk c's group complete
        } else {
            CP_WAIT(0);
        }
        __syncthreads();

        const uint32_t Bb = smb + B_OFF(c & 1);
        #pragma unroll 4
        for (int ks = 0; ks < 16; ++ks) {
            const int q0 = 2 * ks;
            uint32_t a0[4], a1[4], bf0[4], bf1[4];
            {
                int r = r0 + a_r;
                LDSM4(a0, smb + A_OFF + r * 512 + (((q0 + a_q) ^ (r & 7)) << 4));
                int r2 = r + 16;
                LDSM4(a1, smb + A_OFF + r2 * 512 + (((q0 + a_q) ^ (r2 & 7)) << 4));
            }
            {
                int cr = c0t + b_r;
                LDSM4(bf0, Bb + cr * 512 + (((q0 + b_q) ^ (cr & 7)) << 4));
                int cr2 = cr + 16;
                LDSM4(bf1, Bb + cr2 * 512 + (((q0 + b_q) ^ (cr2 & 7)) << 4));
            }
            MMA_BF16(acc[0][0], a0, bf0[0], bf0[1]);
            MMA_BF16(acc[0][1], a0, bf0[2], bf0[3]);
            MMA_BF16(acc[0][2], a0, bf1[0], bf1[1]);
            MMA_BF16(acc[0][3], a0, bf1[2], bf1[3]);
            MMA_BF16(acc[1][0], a1, bf0[0], bf0[1]);
            MMA_BF16(acc[1][1], a1, bf0[2], bf0[3]);
            MMA_BF16(acc[1][2], a1, bf1[0], bf1[1]);
            MMA_BF16(acc[1][3], a1, bf1[2], bf1[3]);
        }
        // chunk epilogue: branchless packed top-2 (5 pipelined ops/score)
        #pragma unroll
        for (int nbb = 0; nbb < 4; ++nbb) {
            const int cb = c * 128 + c0t + nbb * 8 + 2 * t;
            const float2 e2 = *(const float2*)(en + cb);
            #pragma unroll
            for (int mb = 0; mb < 2; ++mb) {
                #pragma unroll
                for (int half = 0; half < 2; ++half) {
                    const int rs = mb * 2 + half;
                    float p0 = packsi(fmaf(-2.0f, acc[mb][nbb][half * 2 + 0], e2.x), cb);
                    s2[rs] = fminf(s2[rs], fmaxf(s1[rs], p0));
                    s1[rs] = fminf(s1[rs], p0);
                    float p1 = packsi(fmaf(-2.0f, acc[mb][nbb][half * 2 + 1], e2.y), cb + 1);
                    s2[rs] = fminf(s2[rs], fmaxf(s1[rs], p1));
                    s1[rs] = fminf(s1[rs], p1);
                }
            }
        }
        #pragma unroll
        for (int a = 0; a < 2; ++a)
            #pragma unroll
            for (int b = 0; b < 4; ++b)
                #pragma unroll
                for (int q = 0; q < 4; ++q) acc[a][b][q] = 0.0f;
        __syncthreads();   // all reads of buf (c&1) done before c+2 overwrites
    }

    // ---- merge per-row candidates: 16 owner slots x packed top-2 ----
    float2* ms = (float2*)smem_;              // 128 x 16 x 8B = 16KB
    const int slot = warpN * 4 + t;
    #pragma unroll
    for (int rs = 0; rs < 4; ++rs) {
        int row = r0 + (rs >> 1) * 16 + (rs & 1) * 8 + g;
        ms[row * 16 + slot] = make_float2(s1[rs], s2[rs]);
    }
    __syncthreads();

    if (tid < 128) {
        float b1 = PBIG, b2 = PBIG, b3 = PBIG;
        #pragma unroll
        for (int s = 0; s < 16; ++s) {
            float2 sv = ms[tid * 16 + s];
            float cs[2] = { sv.x, sv.y };
            #pragma unroll
            for (int q = 0; q < 2; ++q) {
                float p = cs[q];
                if (p < b1)      { b3 = b2; b2 = b1; b1 = p; }
                else if (p < b2) { b3 = b2; b2 = p; }
                else if (p < b3) { b3 = p; }
            }
        }
        uint32_t u1 = __float_as_uint(b1), u2 = __float_as_uint(b2),
                 u3 = __float_as_uint(b3);
        int j1 = u1 & 1023, j2 = u2 & 1023, j3 = u3 & 1023;
        float m1 = __uint_as_float(u1 & ~1023u);
        float m2 = __uint_as_float(u2 & ~1023u);
        float m3 = __uint_as_float(u3 & ~1023u);

        const int n = n0 + tid;
        if (m2 - m1 < GAP_TH) {
            int pos = atomicAdd(&g_flag_cnt, 1);
            int pk = j1 | (j2 << 10) | (j3 << 20) | ((m3 - m1 < GAP_TH) ? (1 << 30) : 0);
            g_fr_n[pos] = n;
            g_fr_c[pos] = pk;
        } else {
            g_idx[n] = j1;
            out_idx_f[n] = (float)j1;
        }
    }
}

// ---------------------------------------------------------------------------
// Kernel 1b: exact fp32 re-rank of flagged rows (one warp per row).
// ---------------------------------------------------------------------------
__global__ void __launch_bounds__(256)
recheck_kernel(const float* __restrict__ z, const float* __restrict__ emb,
               float* __restrict__ out_idx_f) {
    const int gw   = (blockIdx.x * 256 + threadIdx.x) >> 5;
    const int lane = threadIdx.x & 31;
    const int nwarp = gridDim.x * 8;
    const int cnt = g_flag_cnt;

    for (int f = gw; f < cnt; f += nwarp) {
        int n  = g_fr_n[f];
        int pk = g_fr_c[f];
        int cand[3];
        cand[0] = pk & 1023;
        cand[1] = (pk >> 10) & 1023;
        cand[2] = (pk >> 20) & 1023;
        int nc = (pk >> 30) ? 3 : 2;

        int b = n >> 12, hw = n & 4095;
        const float* zr = z + (size_t)b * (D_ * HW_) + hw;
        float zv[8];
        #pragma unroll
        for (int i = 0; i < 8; ++i) zv[i] = zr[(size_t)(lane + 32 * i) * HW_];

        float bs = 3.4e38f; int bi = 0;
        for (int q = 0; q < nc; ++q) {
            int cc = cand[q];
            const float* e = emb + cc * D_;
            float p = 0.0f;
            #pragma unroll
            for (int i = 0; i < 8; ++i) p = fmaf(zv[i], e[lane + 32 * i], p);
            #pragma unroll
            for (int off = 16; off > 0; off >>= 1)
                p += __shfl_down_sync(0xffffffffu, p, off);
            if (lane == 0) {
                float s = g_enorm[cc] - 2.0f * p;
                if (s < bs || (s == bs && cc < bi)) { bs = s; bi = cc; }
            }
        }
        if (lane == 0) { g_idx[n] = bi; out_idx_f[n] = (float)bi; }
    }
}

// ---------------------------------------------------------------------------
// Kernel 2: transpose-tiled gather. Block = 32 hw x 256 d for one b.
// ---------------------------------------------------------------------------
__global__ void __launch_bounds__(256)
gather_loss_dw_kernel(const float* __restrict__ z,
                      const float* __restrict__ emb,
                      float* __restrict__ out_q) {
    __shared__ float zt[32][261];
    __shared__ float wsum[8];

    const int tid  = threadIdx.x;
    const int lane = tid & 31;
    const int w    = tid >> 5;

    const int tile = blockIdx.x;          // 0..4095
    const int b    = tile >> 7;
    const int hw0  = (tile & 127) << 5;
    const float* zb = z     + (size_t)b * (D_ * HW_) + hw0;
    float*       ob = out_q + (size_t)b * (D_ * HW_) + hw0;

    #pragma unroll 8
    for (int i = 0; i < 32; ++i) {
        int d = w * 32 + i;
        zt[lane][d] = zb[(size_t)d * HW_ + lane];
    }
    __syncthreads();

    float lsum = 0.0f;
    #pragma unroll
    for (int pass = 0; pass < 4; ++pass) {
        const int hwl = w + 8 * pass;
        const int n   = (b << 12) + hw0 + hwl;
        const int idx = g_idx[n];
        const float* er = emb  + (size_t)idx * D_;
        float*       dr = g_dw + (size_t)idx * D_;
        if (lane == 0) atomicAdd(&g_counts[idx], 1.0f);
        #pragma unroll
        for (int j = 0; j < 8; ++j) {
            int d = lane + 32 * j;
            float zv = zt[hwl][d];
            float q  = er[d];
            float df = zv - q;
            lsum = fmaf(df, df, lsum);
            atomicAdd(&dr[d], zv);
            zt[hwl][d] = q;
        }
    }
    __syncthreads();

    #pragma unroll 8
    for (int i = 0; i < 32; ++i) {
        int d = w * 32 + i;
        ob[(size_t)d * HW_ + lane] = zt[lane][d];
    }

    #pragma unroll
    for (int off = 16; off > 0; off >>= 1)
        lsum += __shfl_down_sync(0xffffffffu, lsum, off);
    if (lane == 0) wsum[w] = lsum;
    __syncthreads();
    if (w == 0) {
        float v = (lane < 8) ? wsum[lane] : 0.0f;
        #pragma unroll
        for (int off = 4; off > 0; off >>= 1)
            v += __shfl_down_sync(0xffffffffu, v, off);
        if (lane == 0) atomicAdd(&g_loss, (double)v);
    }
}

// ---------------------------------------------------------------------------
// Kernel 3: EMA updates + loss finalize
// ---------------------------------------------------------------------------
__global__ void finalize_kernel(const float* __restrict__ ema_cs,
                                const float* __restrict__ ema_emb,
                                float* __restrict__ out) {
    int i = blockIdx.x * 256 + threadIdx.x;
    const float decay = 0.99f;
    const float omd   = (float)(1.0 - 0.99);
    if (i < K_ * D_) out[OUT_EMB + i] = decay * ema_emb[i] + omd * g_dw[i];
    if (i < K_)      out[OUT_CS  + i] = decay * ema_cs[i]  + omd * g_counts[i];
    if (i == 0)      out[OUT_LOSS]    = 0.25f * (float)(g_loss / (double)TOTQ);
}

// ---------------------------------------------------------------------------
extern "C" void kernel_launch(void* const* d_in, const int* in_sizes, int n_in,
                              void* d_out, int out_size) {
    const float* z       = (const float*)d_in[0];
    const float* emb     = (const float*)d_in[1];
    const float* ema_cs  = (const float*)d_in[2];
    const float* ema_emb = (const float*)d_in[3];
    float* out = (float*)d_out;

    static int smem_set = 0;
    if (!smem_set) {
        cudaFuncSetAttribute(mma_argmin_kernel,
                             cudaFuncAttributeMaxDynamicSharedMemorySize, SMEM_TOTAL);
        smem_set = 1;
    }

    prep_kernel<<<1024, 256>>>(emb);
    dummy1_kernel<<<1, 32>>>();
    dummy2_kernel<<<1, 32>>>();
    mma_argmin_kernel<<<N_ / 128, 512, SMEM_TOTAL>>>(z, out + OUT_IDX);
    recheck_kernel<<<256, 256>>>(z, emb, out + OUT_IDX);
    gather_loss_dw_kernel<<<4096, 256>>>(z, emb, out);
    finalize_kernel<<<1024, 256>>>(ema_cs, ema_emb, out);
}